// round 1
// baseline (speedup 1.0000x reference)
#include <cuda_runtime.h>
#include <cuda_bf16.h>

// Problem constants
#define NB 65536   // batch
#define SS 5       // seq len
#define KK 4       // nodes
#define DD 12      // node feat dim
#define HH 48      // lstm hidden == D*K

// Scratch (allocation-free rule: __device__ globals)
__device__ float g_xbuf[SS * HH * NB];   // [s][feat][n]  (63 MB)
__device__ float g_hfw[HH * NB];         // forward LSTM final hidden, [feat][n]

__device__ __forceinline__ float sigf(float x) {
    return __fdividef(1.0f, 1.0f + __expf(-x));
}
__device__ __forceinline__ float tanhf_(float x) {
    // 1 - 2/(e^{2x}+1): correct saturation at +/-inf, ~1e-7 rel err
    return 1.0f - __fdividef(2.0f, __expf(2.0f * x) + 1.0f);
}

// ===========================================================================
// Kernel A: GNN message passing (2 passes), one thread per (n, s)
// ===========================================================================
__global__ __launch_bounds__(256) void gnn_kernel(
    const float* __restrict__ nf, const float* __restrict__ pos,
    const float* __restrict__ att,
    const float* __restrict__ msgw, const float* __restrict__ msgb,
    const float* __restrict__ gwi, const float* __restrict__ gwh,
    const float* __restrict__ gbi, const float* __restrict__ gbh)
{
    __shared__ float  s_mw[144];
    __shared__ float  s_mb[12];
    __shared__ float4 sA[144];   // [d*12+e] = (wih_r, wih_z, wih_n, whh_r)
    __shared__ float2 sB[144];   // [d*12+e] = (whh_z, whh_n)
    __shared__ float4 sGB[12];   // (b_r, b_z, b_in, b_hn)

    int tid = threadIdx.x;
    for (int i = tid; i < 144; i += 256) {
        s_mw[i] = msgw[i];
        int d = i / 12, e = i - d * 12;
        sA[i] = make_float4(gwi[d * 12 + e], gwi[(12 + d) * 12 + e],
                            gwi[(24 + d) * 12 + e], gwh[d * 12 + e]);
        sB[i] = make_float2(gwh[(12 + d) * 12 + e], gwh[(24 + d) * 12 + e]);
    }
    if (tid < 12) {
        s_mb[tid] = msgb[tid];
        sGB[tid] = make_float4(gbi[tid] + gbh[tid],
                               gbi[12 + tid] + gbh[12 + tid],
                               gbi[24 + tid], gbh[24 + tid]);
    }
    __syncthreads();

    int n = blockIdx.x * 256 + tid;
    int s = blockIdx.y;
    int base = n * SS + s;

    // h[k][d] in registers: node_feat = concat(nodes_feature, pos)
    float h[KK][DD];
    {
        float t[24];
        const float4* p4 = reinterpret_cast<const float4*>(nf + (size_t)base * 24);
        #pragma unroll
        for (int i = 0; i < 6; i++) {
            float4 v = p4[i];
            t[4 * i] = v.x; t[4 * i + 1] = v.y; t[4 * i + 2] = v.z; t[4 * i + 3] = v.w;
        }
        #pragma unroll
        for (int i = 0; i < 24; i++) h[i / 6][i % 6] = t[i];
        const float4* q4 = reinterpret_cast<const float4*>(pos + (size_t)base * 24);
        #pragma unroll
        for (int i = 0; i < 6; i++) {
            float4 v = q4[i];
            t[4 * i] = v.x; t[4 * i + 1] = v.y; t[4 * i + 2] = v.z; t[4 * i + 3] = v.w;
        }
        #pragma unroll
        for (int i = 0; i < 24; i++) h[i / 6][6 + i % 6] = t[i];
    }
    float a[KK][KK];
    {
        const float4* a4 = reinterpret_cast<const float4*>(att + (size_t)base * 16);
        #pragma unroll
        for (int k = 0; k < 4; k++) {
            float4 v = a4[k];
            a[k][0] = v.x; a[k][1] = v.y; a[k][2] = v.z; a[k][3] = v.w;
        }
    }

    #pragma unroll 1
    for (int pass = 0; pass < 2; pass++) {
        // stash h in local memory for the single dynamic-index use (z*h term)
        float hl[48];
        #pragma unroll
        for (int k = 0; k < 4; k++)
            #pragma unroll
            for (int d = 0; d < 12; d++) hl[k * 12 + d] = h[k][d];

        // m_all (per d, transient) -> m_v  (attention-weighted neighbor sum)
        float mv[KK][DD];
        #pragma unroll
        for (int d = 0; d < 12; d++) {
            float ma[4];
            #pragma unroll
            for (int w = 0; w < 4; w++) {
                float acc = s_mb[d];
                #pragma unroll
                for (int e = 0; e < 12; e++) acc += s_mw[d * 12 + e] * h[w][e];
                ma[w] = acc;
            }
            #pragma unroll
            for (int k = 0; k < 4; k++)
                mv[k][d] = a[k][0] * ma[0] + a[k][1] * ma[1] +
                           a[k][2] * ma[2] + a[k][3] * ma[3];
        }

        // GRU per node
        #pragma unroll
        for (int k = 0; k < 4; k++) {
            float tmp[12];
            #pragma unroll 1
            for (int d = 0; d < 12; d++) {
                float4 gb = sGB[d];
                float ir = 0.f, iz = 0.f, innv = 0.f, hr = 0.f, hz = 0.f, hnv = 0.f;
                #pragma unroll
                for (int e = 0; e < 12; e++) {
                    float4 a4 = sA[d * 12 + e];
                    float2 b2 = sB[d * 12 + e];
                    float m = mv[k][e], hv = h[k][e];
                    ir += a4.x * m;  iz += a4.y * m;  innv += a4.z * m;
                    hr += a4.w * hv; hz += b2.x * hv; hnv += b2.y * hv;
                }
                float r = sigf(ir + hr + gb.x);
                float z = sigf(iz + hz + gb.y);
                float nn = tanhf_(innv + gb.z + r * (hnv + gb.w));
                tmp[d] = (1.0f - z) * nn + z * hl[k * 12 + d];
            }
            #pragma unroll
            for (int d = 0; d < 12; d++) h[k][d] = tmp[d];
        }
    }

    // write x = transpose(h,(feat,node)).reshape : x[d*4+k] = h[k][d]
    // layout [s][feat][n] -> coalesced for LSTM kernel
    #pragma unroll
    for (int k = 0; k < 4; k++)
        #pragma unroll
        for (int d = 0; d < 12; d++)
            g_xbuf[(size_t)(s * HH + d * 4 + k) * NB + n] = h[k][d];
}

// ===========================================================================
// Kernel B: bidirectional LSTM + MLP, one thread per n
//   SMEM: packed gate-quad LSTM weights (one direction at a time) + MLP
// ===========================================================================
#define SWQ_N   4608          // 2 * 48 * 48 float4 (ih then hh)
#define SMEM_B_BYTES (SWQ_N*16 + 48*16 + (4608+48+1728+36+216+6)*4)

__global__ __launch_bounds__(256) void lstm_mlp_kernel(
    const float* __restrict__ wihF, const float* __restrict__ whhF,
    const float* __restrict__ bihF, const float* __restrict__ bhhF,
    const float* __restrict__ wihB, const float* __restrict__ whhB,
    const float* __restrict__ bihB, const float* __restrict__ bhhB,
    const float* __restrict__ e1w, const float* __restrict__ e1b,
    const float* __restrict__ e2w, const float* __restrict__ e2b,
    const float* __restrict__ e3w, const float* __restrict__ e3b,
    float* __restrict__ out)
{
    extern __shared__ float smem[];
    float4* swq = reinterpret_cast<float4*>(smem);       // [m][d][j] gate-quads
    float4* sbq = swq + SWQ_N;                           // 48 bias quads
    float*  sm1  = reinterpret_cast<float*>(sbq + 48);   // en1_w [48][96]
    float*  sm1b = sm1 + 4608;
    float*  sm2  = sm1b + 48;                            // en2_w [36][48]
    float*  sm2b = sm2 + 1728;
    float*  sm3  = sm2b + 36;                            // en3_w [6][36]
    float*  sm3b = sm3 + 216;

    int tid = threadIdx.x;
    int n = blockIdx.x * 256 + tid;

    // MLP weights (resident for whole kernel)
    for (int i = tid; i < 4608; i += 256) sm1[i] = e1w[i];
    for (int i = tid; i < 1728; i += 256) sm2[i] = e2w[i];
    for (int i = tid; i < 216;  i += 256) sm3[i] = e3w[i];
    if (tid < 48) sm1b[tid] = e1b[tid];
    if (tid < 36) sm2b[tid] = e2b[tid];
    if (tid < 6)  sm3b[tid] = e3b[tid];

    float x[48];      // registers (constant-indexed only)
    float h[48];      // registers
    float c_l[48];    // local (dynamic index, tiny traffic)
    float hn_l[48];   // local

    #pragma unroll 1
    for (int dir = 0; dir < 2; dir++) {
        const float* wih = dir ? wihB : wihF;
        const float* whh = dir ? whhB : whhF;
        const float* bih = dir ? bihB : bihF;
        const float* bhh = dir ? bhhB : bhhF;

        __syncthreads();   // previous phase done before overwriting weights
        for (int idx = tid; idx < SWQ_N; idx += 256) {
            int m = idx / 2304;
            int r = idx - m * 2304;
            int d = r / 48;
            int j = r - d * 48;
            const float* W = m ? whh : wih;
            swq[idx] = make_float4(W[d * 48 + j], W[(48 + d) * 48 + j],
                                   W[(96 + d) * 48 + j], W[(144 + d) * 48 + j]);
        }
        if (tid < 48)
            sbq[tid] = make_float4(bih[tid] + bhh[tid],
                                   bih[48 + tid] + bhh[48 + tid],
                                   bih[96 + tid] + bhh[96 + tid],
                                   bih[144 + tid] + bhh[144 + tid]);
        __syncthreads();

        #pragma unroll
        for (int j = 0; j < 48; j++) h[j] = 0.f;
        for (int j = 0; j < 48; j++) c_l[j] = 0.f;

        #pragma unroll 1
        for (int st = 0; st < SS; st++) {
            int s = dir ? (SS - 1 - st) : st;
            #pragma unroll
            for (int j = 0; j < 48; j++)
                x[j] = g_xbuf[(size_t)(s * HH + j) * NB + n];

            #pragma unroll 1
            for (int d = 0; d < 48; d++) {
                float4 bb = sbq[d];
                float aI = bb.x, aF = bb.y, aG = bb.z, aO = bb.w;
                const float4* wi = swq + d * 48;
                const float4* wh = swq + 2304 + d * 48;
                #pragma unroll
                for (int j = 0; j < 48; j++) {
                    float4 wiv = wi[j];
                    float4 whv = wh[j];
                    float xv = x[j], hv = h[j];
                    aI += wiv.x * xv; aF += wiv.y * xv;
                    aG += wiv.z * xv; aO += wiv.w * xv;
                    aI += whv.x * hv; aF += whv.y * hv;
                    aG += whv.z * hv; aO += whv.w * hv;
                }
                float ig = sigf(aI), fg = sigf(aF);
                float gg = tanhf_(aG), og = sigf(aO);
                float cn = fg * c_l[d] + ig * gg;
                c_l[d] = cn;
                hn_l[d] = og * tanhf_(cn);
            }
            #pragma unroll
            for (int j = 0; j < 48; j++) h[j] = hn_l[j];
        }

        if (dir == 0) {
            #pragma unroll
            for (int j = 0; j < 48; j++) g_hfw[(size_t)j * NB + n] = h[j];
        }
    }

    // ---- MLP: hn = [h_fw(x), h_bw(h)] ----
    #pragma unroll
    for (int j = 0; j < 48; j++) x[j] = g_hfw[(size_t)j * NB + n];

    float e1_l[48];
    #pragma unroll 1
    for (int i = 0; i < 48; i++) {
        float acc = sm1b[i];
        const float4* w4 = reinterpret_cast<const float4*>(sm1 + i * 96);
        #pragma unroll
        for (int q = 0; q < 12; q++) {
            float4 w = w4[q];
            acc += w.x * x[4 * q] + w.y * x[4 * q + 1] + w.z * x[4 * q + 2] + w.w * x[4 * q + 3];
        }
        #pragma unroll
        for (int q = 0; q < 12; q++) {
            float4 w = w4[12 + q];
            acc += w.x * h[4 * q] + w.y * h[4 * q + 1] + w.z * h[4 * q + 2] + w.w * h[4 * q + 3];
        }
        e1_l[i] = fmaxf(acc, 0.f);
    }
    #pragma unroll
    for (int j = 0; j < 48; j++) x[j] = e1_l[j];

    float e2_l[36];
    #pragma unroll 1
    for (int i = 0; i < 36; i++) {
        float acc = sm2b[i];
        const float4* w4 = reinterpret_cast<const float4*>(sm2 + i * 48);
        #pragma unroll
        for (int q = 0; q < 12; q++) {
            float4 w = w4[q];
            acc += w.x * x[4 * q] + w.y * x[4 * q + 1] + w.z * x[4 * q + 2] + w.w * x[4 * q + 3];
        }
        e2_l[i] = fmaxf(acc, 0.f);
    }
    #pragma unroll
    for (int j = 0; j < 36; j++) h[j] = e2_l[j];

    #pragma unroll
    for (int c = 0; c < 6; c++) {
        float acc = sm3b[c];
        #pragma unroll
        for (int j = 0; j < 36; j++) acc += sm3[c * 36 + j] * h[j];
        out[(size_t)n * 6 + c] = acc;
    }
}

// ===========================================================================
extern "C" void kernel_launch(void* const* d_in, const int* in_sizes, int n_in,
                              void* d_out, int out_size)
{
    const float* nf   = (const float*)d_in[0];
    const float* pos  = (const float*)d_in[1];
    const float* att  = (const float*)d_in[2];
    const float* msgw = (const float*)d_in[3];
    const float* msgb = (const float*)d_in[4];
    const float* gwi  = (const float*)d_in[5];
    const float* gwh  = (const float*)d_in[6];
    const float* gbi  = (const float*)d_in[7];
    const float* gbh  = (const float*)d_in[8];
    const float* wihF = (const float*)d_in[9];
    const float* whhF = (const float*)d_in[10];
    const float* bihF = (const float*)d_in[11];
    const float* bhhF = (const float*)d_in[12];
    const float* wihB = (const float*)d_in[13];
    const float* whhB = (const float*)d_in[14];
    const float* bihB = (const float*)d_in[15];
    const float* bhhB = (const float*)d_in[16];
    const float* e1w  = (const float*)d_in[17];
    const float* e1b  = (const float*)d_in[18];
    const float* e2w  = (const float*)d_in[19];
    const float* e2b  = (const float*)d_in[20];
    const float* e3w  = (const float*)d_in[21];
    const float* e3b  = (const float*)d_in[22];
    float* out = (float*)d_out;

    cudaFuncSetAttribute(lstm_mlp_kernel,
                         cudaFuncAttributeMaxDynamicSharedMemorySize,
                         SMEM_B_BYTES);

    dim3 gA(NB / 256, SS);
    gnn_kernel<<<gA, 256>>>(nf, pos, att, msgw, msgb, gwi, gwh, gbi, gbh);
    lstm_mlp_kernel<<<NB / 256, 256, SMEM_B_BYTES>>>(
        wihF, whhF, bihF, bhhF, wihB, whhB, bihB, bhhB,
        e1w, e1b, e2w, e2b, e3w, e3b, out);
}